// round 1
// baseline (speedup 1.0000x reference)
#include <cuda_runtime.h>
#include <math.h>

#define DE    100
#define DR    100
#define RK    40
#define NENT  10000
#define BATCH 128
#define KDIM  1600          // RK*RK
#define MN    10000         // DE*DE
#define FSTR  (DE*RK)       // 4000, stride of first index in factor tensors

// ---------- device scratch (static: no allocations allowed) ----------
__device__ float g_Amat [MN * KDIM];   // 64 MB  [(i*100+j), (a*40+c)]
__device__ float g_CmatT[MN * KDIM];   // 64 MB  [(k*100+l), (a*40+c)]
__device__ float g_rbn  [BATCH * DR];
__device__ float g_e1bn [BATCH * DE];
__device__ float g_e2bn [BATCH * DE];
__device__ float g_wout [BATCH * DE];
__device__ float g_woutbn[BATCH * DE];
__device__ float g_scores[BATCH * NENT];

// ---------------------------------------------------------------------
// Amat / CmatT construction.
// swap==0: out[(p*100+q)*1600 + a*40+c] = sum_b X[a,p,b] * Y[b,q,c]   (Amat: X=f0,Y=f1)
// swap==1: out[(p*100+q)*1600 + a*40+c] = sum_b X[c,p,b] * Y[b,q,a]   (CmatT: X=f2,Y=f3)
__global__ __launch_bounds__(256) void pair_contract(const float* __restrict__ X,
                                                     const float* __restrict__ Y,
                                                     int swap)
{
    __shared__ float Xs[RK][RK + 1];
    __shared__ float Ys[RK][RK + 1];
    float* out = swap ? g_CmatT : g_Amat;
    const int p = blockIdx.x / DE;
    const int q = blockIdx.x % DE;
    const int t = threadIdx.x;

    for (int lin = t; lin < RK * RK; lin += 256) {
        int u = lin / RK, w = lin % RK;
        Xs[u][w] = X[u * FSTR + p * RK + w];
        Ys[u][w] = Y[u * FSTR + q * RK + w];
    }
    __syncthreads();

    for (int lin = t; lin < RK * RK; lin += 256) {
        int a = lin / RK, c = lin % RK;
        int uu = swap ? c : a;
        int vv = swap ? a : c;
        float s = 0.f;
#pragma unroll
        for (int b = 0; b < RK; b++) s += Xs[uu][b] * Ys[b][vv];
        out[(size_t)blockIdx.x * KDIM + lin] = s;
    }
}

// ---------------------------------------------------------------------
// BatchNorm1d (training mode, biased variance) over the batch dim.
// grid = D columns, block = 128 (= BATCH) threads.
// table==nullptr -> normalize g_wout rows (idx ignored, row = threadIdx).
// dst_sel: 0->g_rbn 1->g_e1bn 2->g_e2bn 3->g_woutbn
__global__ __launch_bounds__(128) void bn_kernel(const float* __restrict__ table,
                                                 const int* __restrict__ idx,
                                                 const float* __restrict__ gamma,
                                                 const float* __restrict__ beta,
                                                 int D, int dst_sel)
{
    const int col = blockIdx.x;
    const int b   = threadIdx.x;          // 0..127
    float* out = (dst_sel == 0) ? g_rbn :
                 (dst_sel == 1) ? g_e1bn :
                 (dst_sel == 2) ? g_e2bn : g_woutbn;

    float x;
    if (table) {
        int row = idx[b];
        x = table[(size_t)row * D + col];
    } else {
        x = g_wout[b * D + col];
    }

    __shared__ float ssum[4], ssq[4];
    __shared__ float smu, srs;
    float s = x, sq = x * x;
#pragma unroll
    for (int o = 16; o > 0; o >>= 1) {
        s  += __shfl_down_sync(0xffffffffu, s, o);
        sq += __shfl_down_sync(0xffffffffu, sq, o);
    }
    int wid = b >> 5, lid = b & 31;
    if (lid == 0) { ssum[wid] = s; ssq[wid] = sq; }
    __syncthreads();
    if (b == 0) {
        float ts = ssum[0] + ssum[1] + ssum[2] + ssum[3];
        float tq = ssq[0]  + ssq[1]  + ssq[2]  + ssq[3];
        float mu  = ts * (1.f / BATCH);
        float var = tq * (1.f / BATCH) - mu * mu;
        smu = mu;
        srs = rsqrtf(var + 1e-5f);
    }
    __syncthreads();
    out[b * D + col] = gamma[col] * (x - smu) * srs + beta[col];
}

// ---------------------------------------------------------------------
// Fused per-batch tensor-ring contraction for W_out (avoids the 512 MB W_mat):
// W_out[bt,j] = sum_{a,b,c,d} u0[a,b] v1[b,c] f2[c,j,d] v3[d,a]
__global__ __launch_bounds__(256) void tr_wout_kernel(const float* __restrict__ f0,
                                                      const float* __restrict__ f1,
                                                      const float* __restrict__ f2,
                                                      const float* __restrict__ f3)
{
    const int bt = blockIdx.x;
    const int t  = threadIdx.x;
    __shared__ float rv[DR], e1v[DE], e2v[DE];
    __shared__ float u0[KDIM], v1[KDIM], v3[KDIM], m2[KDIM], q2[KDIM];

    if (t < DR) rv[t]  = g_rbn [bt * DR + t];
    if (t < DE) { e1v[t] = g_e1bn[bt * DE + t]; e2v[t] = g_e2bn[bt * DE + t]; }
    __syncthreads();

    // u0[a,b] = sum_r rv[r]  f0[a,r,b]
    // v1[b,c] = sum_i e1v[i] f1[b,i,c]
    // v3[d,a] = sum_k e2v[k] f3[d,k,a]
    for (int lin = t; lin < KDIM; lin += 256) {
        int u = lin / RK, w = lin % RK;
        float s0 = 0.f, s1 = 0.f, s3 = 0.f;
        for (int r = 0; r < DR; r++) {
            s0 += rv[r]  * f0[u * FSTR + r * RK + w];
            s1 += e1v[r] * f1[u * FSTR + r * RK + w];
            s3 += e2v[r] * f3[u * FSTR + r * RK + w];
        }
        u0[lin] = s0; v1[lin] = s1; v3[lin] = s3;
    }
    __syncthreads();

    // m2[a,c] = sum_b u0[a,b] v1[b,c]
    for (int lin = t; lin < KDIM; lin += 256) {
        int a = lin / RK, c = lin % RK;
        float s = 0.f;
#pragma unroll
        for (int b = 0; b < RK; b++) s += u0[a * RK + b] * v1[b * RK + c];
        m2[lin] = s;
    }
    __syncthreads();

    // q2[c,d] = sum_a m2[a,c] v3[d,a]
    for (int lin = t; lin < KDIM; lin += 256) {
        int c = lin / RK, d = lin % RK;
        float s = 0.f;
#pragma unroll
        for (int a = 0; a < RK; a++) s += m2[a * RK + c] * v3[d * RK + a];
        q2[lin] = s;
    }
    __syncthreads();

    // W_out[j] = sum_{c,d} q2[c,d] f2[c,j,d]
    if (t < DE) {
        float s = 0.f;
        for (int c = 0; c < RK; c++) {
            const float* f2row = f2 + c * FSTR + t * RK;
#pragma unroll
            for (int d = 0; d < RK; d++) s += q2[c * RK + d] * f2row[d];
        }
        g_wout[bt * DE + t] = s;
    }
}

// ---------------------------------------------------------------------
// scores[bt,e] = sum_i woutbn[bt,i] * E[e,i]
__global__ __launch_bounds__(256) void scores_kernel(const float* __restrict__ E)
{
    const int bt = blockIdx.x;
    const int t  = threadIdx.x;
    __shared__ float wv[DE];
    if (t < DE) wv[t] = g_woutbn[bt * DE + t];
    __syncthreads();
    for (int e = t; e < NENT; e += 256) {
        const float* er = E + (size_t)e * DE;
        float s = 0.f;
#pragma unroll 4
        for (int i = 0; i < DE; i++) s += wv[i] * er[i];
        g_scores[(size_t)bt * NENT + e] = s;
    }
}

// ---------------------------------------------------------------------
__global__ __launch_bounds__(256) void softmax_kernel(float* __restrict__ pred)
{
    const int bt = blockIdx.x;
    const int t  = threadIdx.x;
    const float* row = g_scores + (size_t)bt * NENT;
    __shared__ float red[8];
    __shared__ float smx, ssum;

    float mx = -1e30f;
    for (int e = t; e < NENT; e += 256) mx = fmaxf(mx, row[e]);
#pragma unroll
    for (int o = 16; o > 0; o >>= 1) mx = fmaxf(mx, __shfl_xor_sync(0xffffffffu, mx, o));
    if ((t & 31) == 0) red[t >> 5] = mx;
    __syncthreads();
    if (t == 0) {
        float m = red[0];
        for (int i = 1; i < 8; i++) m = fmaxf(m, red[i]);
        smx = m;
    }
    __syncthreads();
    mx = smx;

    float sum = 0.f;
    for (int e = t; e < NENT; e += 256) sum += expf(row[e] - mx);
#pragma unroll
    for (int o = 16; o > 0; o >>= 1) sum += __shfl_xor_sync(0xffffffffu, sum, o);
    __syncthreads();
    if ((t & 31) == 0) red[t >> 5] = sum;
    __syncthreads();
    if (t == 0) {
        float s = 0.f;
        for (int i = 0; i < 8; i++) s += red[i];
        ssum = s;
    }
    __syncthreads();
    const float inv = 1.f / ssum;
    for (int e = t; e < NENT; e += 256)
        pred[(size_t)bt * NENT + e] = expf(row[e] - mx) * inv;
}

// ---------------------------------------------------------------------
// W = Amat (10000x1600, K-major) * CmatT^T (10000x1600, K-major)  -> 10000x10000
// Classic 128x128x16 register-blocked fp32 TN SGEMM, 8x8 per thread.
#define BM 128
#define BN 128
#define BK 16
__global__ __launch_bounds__(256) void sgemm_tn(float* __restrict__ C, int M, int N, int K)
{
    const float* __restrict__ A = g_Amat;
    const float* __restrict__ B = g_CmatT;

    __shared__ __align__(16) float As[BK][BM + 4];
    __shared__ __align__(16) float Bs[BK][BN + 4];

    const int t  = threadIdx.x;
    const int m0 = blockIdx.y * BM;
    const int n0 = blockIdx.x * BN;
    const int tx = t & 15;
    const int ty = t >> 4;

    float acc[8][8];
#pragma unroll
    for (int i = 0; i < 8; i++)
#pragma unroll
        for (int j = 0; j < 8; j++) acc[i][j] = 0.f;

    for (int k0 = 0; k0 < K; k0 += BK) {
#pragma unroll
        for (int rep = 0; rep < 2; rep++) {
            int idx = t + rep * 256;
            int row = idx >> 2;            // 0..127
            int kq  = (idx & 3) << 2;      // 0,4,8,12
            float4 av = make_float4(0.f, 0.f, 0.f, 0.f);
            float4 bv = make_float4(0.f, 0.f, 0.f, 0.f);
            int gm = m0 + row, gn = n0 + row;
            if (gm < M) av = *reinterpret_cast<const float4*>(A + (size_t)gm * K + k0 + kq);
            if (gn < N) bv = *reinterpret_cast<const float4*>(B + (size_t)gn * K + k0 + kq);
            As[kq + 0][row] = av.x; As[kq + 1][row] = av.y;
            As[kq + 2][row] = av.z; As[kq + 3][row] = av.w;
            Bs[kq + 0][row] = bv.x; Bs[kq + 1][row] = bv.y;
            Bs[kq + 2][row] = bv.z; Bs[kq + 3][row] = bv.w;
        }
        __syncthreads();

#pragma unroll
        for (int kk = 0; kk < BK; kk++) {
            float a[8], b[8];
            float4 a0 = *reinterpret_cast<const float4*>(&As[kk][ty * 8]);
            float4 a1 = *reinterpret_cast<const float4*>(&As[kk][ty * 8 + 4]);
            float4 b0 = *reinterpret_cast<const float4*>(&Bs[kk][tx * 8]);
            float4 b1 = *reinterpret_cast<const float4*>(&Bs[kk][tx * 8 + 4]);
            a[0]=a0.x; a[1]=a0.y; a[2]=a0.z; a[3]=a0.w;
            a[4]=a1.x; a[5]=a1.y; a[6]=a1.z; a[7]=a1.w;
            b[0]=b0.x; b[1]=b0.y; b[2]=b0.z; b[3]=b0.w;
            b[4]=b1.x; b[5]=b1.y; b[6]=b1.z; b[7]=b1.w;
#pragma unroll
            for (int i = 0; i < 8; i++)
#pragma unroll
                for (int j = 0; j < 8; j++) acc[i][j] = fmaf(a[i], b[j], acc[i][j]);
        }
        __syncthreads();
    }

    if (m0 + BM <= M && n0 + BN <= N) {
#pragma unroll
        for (int i = 0; i < 8; i++) {
            float* cp = C + (size_t)(m0 + ty * 8 + i) * N + n0 + tx * 8;
            float4 v0 = make_float4(acc[i][0], acc[i][1], acc[i][2], acc[i][3]);
            float4 v1 = make_float4(acc[i][4], acc[i][5], acc[i][6], acc[i][7]);
            *reinterpret_cast<float4*>(cp)     = v0;
            *reinterpret_cast<float4*>(cp + 4) = v1;
        }
    } else {
#pragma unroll
        for (int i = 0; i < 8; i++) {
            int gm = m0 + ty * 8 + i;
            if (gm >= M) continue;
#pragma unroll
            for (int j = 0; j < 8; j++) {
                int gn = n0 + tx * 8 + j;
                if (gn < N) C[(size_t)gm * N + gn] = acc[i][j];
            }
        }
    }
}

// ---------------------------------------------------------------------
extern "C" void kernel_launch(void* const* d_in, const int* in_sizes, int n_in,
                              void* d_out, int out_size)
{
    const float* E     = (const float*)d_in[0];
    const float* R     = (const float*)d_in[1];
    const float* f0    = (const float*)d_in[2];
    const float* f1    = (const float*)d_in[3];
    const float* f2    = (const float*)d_in[4];
    const float* f3    = (const float*)d_in[5];
    const float* bnr_g = (const float*)d_in[6];
    const float* bnr_b = (const float*)d_in[7];
    const float* bne_g = (const float*)d_in[8];
    const float* bne_b = (const float*)d_in[9];
    const float* bnw_g = (const float*)d_in[10];
    const float* bnw_b = (const float*)d_in[11];
    const int*   r_idx = (const int*)d_in[12];
    const int*   e_idx1 = (const int*)d_in[13];
    const int*   e_idx2 = (const int*)d_in[14];
    // d_in[15] = miss_ent_domain (always 2 for this problem's inputs)

    float* outPred = (float*)d_out;                 // [128, 10000]
    float* outW    = outPred + (size_t)BATCH * NENT; // [100,100,100,100]

    // --- TR tensor reconstruction operands ---
    pair_contract<<<MN, 256>>>(f0, f1, 0);   // Amat
    pair_contract<<<MN, 256>>>(f2, f3, 1);   // CmatT

    // --- prediction path (cheap) ---
    bn_kernel<<<DR, 128>>>(R, r_idx,  bnr_g, bnr_b, DR, 0);
    bn_kernel<<<DE, 128>>>(E, e_idx1, bne_g, bne_b, DE, 1);
    bn_kernel<<<DE, 128>>>(E, e_idx2, bne_g, bne_b, DE, 2);
    tr_wout_kernel<<<BATCH, 256>>>(f0, f1, f2, f3);
    bn_kernel<<<DE, 128>>>(nullptr, nullptr, bnw_g, bnw_b, DE, 3);
    scores_kernel<<<BATCH, 256>>>(E);
    softmax_kernel<<<BATCH, 256>>>(outPred);

    // --- the big one: W = Amat @ CmatT^T  (320 GFLOP fp32) ---
    dim3 grid((NENT + BN - 1) / BN, (NENT + BM - 1) / BM);
    sgemm_tn<<<grid, 256>>>(outW, MN, MN, KDIM);
}

// round 4
// speedup vs baseline: 2.3903x; 2.3903x over previous
#include <cuda_runtime.h>
#include <cuda_bf16.h>
#include <math.h>
#include <stdint.h>

#define DE    100
#define DR    100
#define RK    40
#define NENT  10000
#define BATCH 128
#define KDIM  1600          // RK*RK
#define MN    10000         // DE*DE
#define FSTR  (DE*RK)       // 4000
#define KBIG  4800          // [hi|hi|lo] / [hi|lo|hi] concatenated K (bf16)
#define BKC   64            // bf16 per K-chunk (128 B row)
#define NCHUNK (KBIG/BKC)   // 75
#define NSTG  3

// GEMM tile
#define BM 128
#define BN 256
#define STAGE_A (BM*128)              // 16384 B
#define STAGE_B (BN*128)              // 32768 B
#define STAGE_BYTES (STAGE_A+STAGE_B) // 49152 B
#define SMEM_TOTAL (NSTG*STAGE_BYTES) // 147456 B

// ---------- device scratch ----------
__device__ __nv_bfloat16 g_Abig[(size_t)MN * KBIG];  // 96 MB
__device__ __nv_bfloat16 g_Bbig[(size_t)MN * KBIG];  // 96 MB
__device__ float g_rbn  [BATCH * DR];
__device__ float g_e1bn [BATCH * DE];
__device__ float g_e2bn [BATCH * DE];
__device__ float g_wout [BATCH * DE];
__device__ float g_woutbn[BATCH * DE];
__device__ float g_scores[BATCH * NENT];

// ==================== helpers ====================
__device__ __forceinline__ uint32_t smem_u32(const void* p) {
    uint32_t a;
    asm("{ .reg .u64 t; cvta.to.shared.u64 t, %1; cvt.u32.u64 %0, t; }" : "=r"(a) : "l"(p));
    return a;
}
__device__ __forceinline__ void cp16(uint32_t dst, const void* src) {
    asm volatile("cp.async.cg.shared.global [%0], [%1], 16;\n" :: "r"(dst), "l"(src) : "memory");
}
__device__ __forceinline__ void cp_commit() {
    asm volatile("cp.async.commit_group;" ::: "memory");
}
template <int N>
__device__ __forceinline__ void cp_wait() {
    asm volatile("cp.async.wait_group %0;" :: "n"(N) : "memory");
}
__device__ __forceinline__ void ldsm_x4(uint32_t& r0, uint32_t& r1, uint32_t& r2, uint32_t& r3, uint32_t addr) {
    asm volatile("ldmatrix.sync.aligned.m8n8.x4.shared.b16 {%0,%1,%2,%3}, [%4];"
                 : "=r"(r0), "=r"(r1), "=r"(r2), "=r"(r3) : "r"(addr));
}
__device__ __forceinline__ void mma16816(float* c, const uint32_t* a, uint32_t b0, uint32_t b1) {
    asm volatile(
        "mma.sync.aligned.m16n8k16.row.col.f32.bf16.bf16.f32 "
        "{%0,%1,%2,%3}, {%4,%5,%6,%7}, {%8,%9}, {%0,%1,%2,%3};"
        : "+f"(c[0]), "+f"(c[1]), "+f"(c[2]), "+f"(c[3])
        : "r"(a[0]), "r"(a[1]), "r"(a[2]), "r"(a[3]), "r"(b0), "r"(b1));
}

// ---------------------------------------------------------------------
// Amat / CmatT construction -> bf16 hi/lo, 3-segment K concatenation.
//   Abig row = [hi | hi | lo]     Bbig row = [hi | lo | hi]
// so segment-wise TN dot = hi.hi + hi.lo + lo.hi  (drops only lo.lo ~2^-16)
// swap==0: val[(p,q)][a*40+c] = sum_b f0[a,p,b] f1[b,q,c]   (Abig)
// swap==1: val[(p,q)][a*40+c] = sum_b f2[c,p,b] f3[b,q,a]   (Bbig)
__global__ __launch_bounds__(256) void pair_contract(const float* __restrict__ X,
                                                     const float* __restrict__ Y,
                                                     int swap)
{
    __shared__ float Xs[RK][RK + 1];
    __shared__ float Ys[RK][RK + 1];
    __nv_bfloat16* out = swap ? g_Bbig : g_Abig;
    const int p = blockIdx.x / DE;
    const int q = blockIdx.x % DE;
    const int t = threadIdx.x;

    for (int lin = t; lin < RK * RK; lin += 256) {
        int u = lin / RK, w = lin % RK;
        Xs[u][w] = X[u * FSTR + p * RK + w];
        Ys[u][w] = Y[u * FSTR + q * RK + w];
    }
    __syncthreads();

    for (int lin = t; lin < RK * RK; lin += 256) {
        int a = lin / RK, c = lin % RK;
        int uu = swap ? c : a;
        int vv = swap ? a : c;
        float s = 0.f;
#pragma unroll
        for (int b = 0; b < RK; b++) s += Xs[uu][b] * Ys[b][vv];
        __nv_bfloat16 hi = __float2bfloat16(s);
        __nv_bfloat16 lo = __float2bfloat16(s - __bfloat162float(hi));
        size_t rb = (size_t)blockIdx.x * KBIG;
        if (swap == 0) {            // A: [hi | hi | lo]
            out[rb + lin]            = hi;
            out[rb + KDIM + lin]     = hi;
            out[rb + 2 * KDIM + lin] = lo;
        } else {                    // B: [hi | lo | hi]
            out[rb + lin]            = hi;
            out[rb + KDIM + lin]     = lo;
            out[rb + 2 * KDIM + lin] = hi;
        }
    }
}

// ---------------------------------------------------------------------
// W[10000,10000] = Abig @ Bbig^T over K=4800 bf16, fp32 accum.
// mma.sync.m16n8k16 + ldmatrix + 3-stage cp.async. CTA tile 128x256.
// 8 warps as 2(m) x 4(n); warp tile 64x64.
__global__ void __launch_bounds__(256, 1) tn_gemm(float* __restrict__ Wout)
{
    extern __shared__ __align__(1024) char smem[];
    const uint32_t sb = smem_u32(smem);
    const int tid  = threadIdx.x;
    const int lane = tid & 31;
    const int wid  = tid >> 5;
    const int wm   = wid >> 2;       // 0..1
    const int wn   = wid & 3;        // 0..3
    const int m0 = blockIdx.y * BM;
    const int n0 = blockIdx.x * BN;
    const __nv_bfloat16* __restrict__ A = g_Abig;
    const __nv_bfloat16* __restrict__ B = g_Bbig;

    float acc[4][8][4];
#pragma unroll
    for (int i = 0; i < 4; i++)
#pragma unroll
        for (int j = 0; j < 8; j++)
#pragma unroll
            for (int k = 0; k < 4; k++) acc[i][j][k] = 0.f;

    // ---- cp.async stage fill ----
    auto load_stage = [&](int ck, int stg) {
        uint32_t sA = sb + stg * STAGE_BYTES;
        uint32_t sB = sA + STAGE_A;
#pragma unroll
        for (int i = 0; i < 4; i++) {          // A: 1024 chunks of 16B
            int q = tid + i * 256;
            int row = q >> 3, seg = q & 7;
            int gm = m0 + row; if (gm > MN - 1) gm = MN - 1;
            const void* src = A + (size_t)gm * KBIG + ck * BKC + seg * 8;
            cp16(sA + row * 128 + ((seg * 16) ^ ((row & 7) << 4)), src);
        }
#pragma unroll
        for (int i = 0; i < 8; i++) {          // B: 2048 chunks
            int q = tid + i * 256;
            int row = q >> 3, seg = q & 7;
            int gn = n0 + row; if (gn > MN - 1) gn = MN - 1;
            const void* src = B + (size_t)gn * KBIG + ck * BKC + seg * 8;
            cp16(sB + row * 128 + ((seg * 16) ^ ((row & 7) << 4)), src);
        }
        cp_commit();
    };

    // ---- per-thread ldmatrix address pieces ----
    const int aq = lane >> 3;
    const int arow = ((aq & 1) << 3) + (lane & 7);      // + wm*64 + mi*16
    const int akb  = (aq >> 1) << 4;                    // 0 | 16
    const int bq = lane >> 3;
    const int brow = ((bq >> 1) << 3) + (lane & 7);     // + wn*64 + ng*16
    const int bkb  = (bq & 1) << 4;
    const int xm = (lane & 7) << 4;                     // swizzle xor mask

    uint32_t aoff[4], boff[4];
#pragma unroll
    for (int mi = 0; mi < 4; mi++) aoff[mi] = (wm * 64 + mi * 16 + arow) * 128;
#pragma unroll
    for (int ng = 0; ng < 4; ng++) boff[ng] = (wn * 64 + ng * 16 + brow) * 128;
    uint32_t kA[4], kB[4];
#pragma unroll
    for (int ks = 0; ks < 4; ks++) {
        kA[ks] = (uint32_t)((ks * 32 + akb) ^ xm);
        kB[ks] = (uint32_t)((ks * 32 + bkb) ^ xm);
    }

    // ---- pipeline prologue ----
    load_stage(0, 0);
    load_stage(1, 1);

    for (int c = 0; c < NCHUNK; c++) {
        cp_wait<1>();
        __syncthreads();
        if (c + 2 < NCHUNK) load_stage(c + 2, (c + 2) % NSTG);

        uint32_t sA = sb + (c % NSTG) * STAGE_BYTES;
        uint32_t sB = sA + STAGE_A;

#pragma unroll
        for (int ks = 0; ks < 4; ks++) {
            uint32_t a[4][4];
#pragma unroll
            for (int mi = 0; mi < 4; mi++)
                ldsm_x4(a[mi][0], a[mi][1], a[mi][2], a[mi][3], sA + aoff[mi] + kA[ks]);
#pragma unroll
            for (int ng = 0; ng < 4; ng++) {
                uint32_t b0, b1, b2, b3;
                ldsm_x4(b0, b1, b2, b3, sB + boff[ng] + kB[ks]);
#pragma unroll
                for (int mi = 0; mi < 4; mi++) {
                    mma16816(acc[mi][ng * 2 + 0], a[mi], b0, b1);
                    mma16816(acc[mi][ng * 2 + 1], a[mi], b2, b3);
                }
            }
        }
        __syncthreads();
    }

    // ---- epilogue: register fragments -> gmem ----
    const int rb = m0 + wm * 64 + (lane >> 2);
    const int cb = n0 + wn * 64 + 2 * (lane & 3);
#pragma unroll
    for (int mi = 0; mi < 4; mi++) {
        int r0 = rb + mi * 16;
#pragma unroll
        for (int nj = 0; nj < 8; nj++) {
            int cc = cb + nj * 8;
            if (cc < MN) {
                if (r0 < MN) {
                    float2 v = make_float2(acc[mi][nj][0], acc[mi][nj][1]);
                    *reinterpret_cast<float2*>(Wout + (size_t)r0 * MN + cc) = v;
                }
                if (r0 + 8 < MN) {
                    float2 v = make_float2(acc[mi][nj][2], acc[mi][nj][3]);
                    *reinterpret_cast<float2*>(Wout + (size_t)(r0 + 8) * MN + cc) = v;
                }
            }
        }
    }
}

// ---------------------------------------------------------------------
// BatchNorm1d (training mode, biased variance) over the batch dim.
__global__ __launch_bounds__(128) void bn_kernel(const float* __restrict__ table,
                                                 const int* __restrict__ idx,
                                                 const float* __restrict__ gamma,
                                                 const float* __restrict__ beta,
                                                 int D, int dst_sel)
{
    const int col = blockIdx.x;
    const int b   = threadIdx.x;
    float* out = (dst_sel == 0) ? g_rbn :
                 (dst_sel == 1) ? g_e1bn :
                 (dst_sel == 2) ? g_e2bn : g_woutbn;

    float x;
    if (table) {
        int row = idx[b];
        x = table[(size_t)row * D + col];
    } else {
        x = g_wout[b * D + col];
    }

    __shared__ float ssum[4], ssq[4];
    __shared__ float smu, srs;
    float s = x, sq = x * x;
#pragma unroll
    for (int o = 16; o > 0; o >>= 1) {
        s  += __shfl_down_sync(0xffffffffu, s, o);
        sq += __shfl_down_sync(0xffffffffu, sq, o);
    }
    int w = b >> 5, l = b & 31;
    if (l == 0) { ssum[w] = s; ssq[w] = sq; }
    __syncthreads();
    if (b == 0) {
        float ts = ssum[0] + ssum[1] + ssum[2] + ssum[3];
        float tq = ssq[0]  + ssq[1]  + ssq[2]  + ssq[3];
        float mu  = ts * (1.f / BATCH);
        float var = tq * (1.f / BATCH) - mu * mu;
        smu = mu;
        srs = rsqrtf(var + 1e-5f);
    }
    __syncthreads();
    out[b * D + col] = gamma[col] * (x - smu) * srs + beta[col];
}

// ---------------------------------------------------------------------
// Fused per-batch TR contraction for W_out (skips the 512 MB W_mat).
__global__ __launch_bounds__(256) void tr_wout_kernel(const float* __restrict__ f0,
                                                      const float* __restrict__ f1,
                                                      const float* __restrict__ f2,
                                                      const float* __restrict__ f3)
{
    const int bt = blockIdx.x;
    const int t  = threadIdx.x;
    __shared__ float rv[DR], e1v[DE], e2v[DE];
    __shared__ float u0[KDIM], v1[KDIM], v3[KDIM], m2[KDIM], q2[KDIM];

    if (t < DR) rv[t]  = g_rbn [bt * DR + t];
    if (t < DE) { e1v[t] = g_e1bn[bt * DE + t]; e2v[t] = g_e2bn[bt * DE + t]; }
    __syncthreads();

    for (int lin = t; lin < KDIM; lin += 256) {
        int u = lin / RK, w = lin % RK;
        float s0 = 0.f, s1 = 0.f, s3 = 0.f;
        for (int r = 0; r < DR; r++) {
            s0 += rv[r]  * f0[u * FSTR + r * RK + w];
            s1 += e1v[r] * f1[u * FSTR + r * RK + w];
            s3 += e2v[r] * f3[u * FSTR + r * RK + w];
        }
        u0[lin] = s0; v1[lin] = s1; v3[lin] = s3;
    }
    __syncthreads();

    for (int lin = t; lin < KDIM; lin += 256) {
        int a = lin / RK, c = lin % RK;
        float s = 0.f;
#pragma unroll
        for (int b = 0; b < RK; b++) s += u0[a * RK + b] * v1[b * RK + c];
        m2[lin] = s;
    }
    __syncthreads();

    for (int lin = t; lin < KDIM; lin += 256) {
        int c = lin / RK, d = lin % RK;
        float s = 0.f;
#pragma unroll
        for (int a = 0; a < RK; a++) s += m2[a * RK + c] * v3[d * RK + a];
        q2[lin] = s;
    }
    __syncthreads();

    if (t < DE) {
        float s = 0.f;
        for (int c = 0; c < RK; c++) {
            const float* f2row = f2 + c * FSTR + t * RK;
#pragma unroll
            for (int d = 0; d < RK; d++) s += q2[c * RK + d] * f2row[d];
        }
        g_wout[bt * DE + t] = s;
    }
}

// ---------------------------------------------------------------------
__global__ __launch_bounds__(256) void scores_kernel(const float* __restrict__ E)
{
    const int bt = blockIdx.x;
    const int t  = threadIdx.x;
    __shared__ float wv[DE];
    if (t < DE) wv[t] = g_woutbn[bt * DE + t];
    __syncthreads();
    for (int e = t; e < NENT; e += 256) {
        const float* er = E + (size_t)e * DE;
        float s = 0.f;
#pragma unroll 4
        for (int i = 0; i < DE; i++) s += wv[i] * er[i];
        g_scores[(size_t)bt * NENT + e] = s;
    }
}

// ---------------------------------------------------------------------
__global__ __launch_bounds__(256) void softmax_kernel(float* __restrict__ pred)
{
    const int bt = blockIdx.x;
    const int t  = threadIdx.x;
    const float* row = g_scores + (size_t)bt * NENT;
    __shared__ float red[8];
    __shared__ float smx, ssumv;

    float mx = -1e30f;
    for (int e = t; e < NENT; e += 256) mx = fmaxf(mx, row[e]);
#pragma unroll
    for (int o = 16; o > 0; o >>= 1) mx = fmaxf(mx, __shfl_xor_sync(0xffffffffu, mx, o));
    if ((t & 31) == 0) red[t >> 5] = mx;
    __syncthreads();
    if (t == 0) {
        float m = red[0];
        for (int i = 1; i < 8; i++) m = fmaxf(m, red[i]);
        smx = m;
    }
    __syncthreads();
    mx = smx;

    float sum = 0.f;
    for (int e = t; e < NENT; e += 256) sum += expf(row[e] - mx);
#pragma unroll
    for (int o = 16; o > 0; o >>= 1) sum += __shfl_xor_sync(0xffffffffu, sum, o);
    __syncthreads();
    if ((t & 31) == 0) red[t >> 5] = sum;
    __syncthreads();
    if (t == 0) {
        float s = 0.f;
        for (int i = 0; i < 8; i++) s += red[i];
        ssumv = s;
    }
    __syncthreads();
    const float inv = 1.f / ssumv;
    for (int e = t; e < NENT; e += 256)
        pred[(size_t)bt * NENT + e] = expf(row[e] - mx) * inv;
}

// ---------------------------------------------------------------------
extern "C" void kernel_launch(void* const* d_in, const int* in_sizes, int n_in,
                              void* d_out, int out_size)
{
    const float* E     = (const float*)d_in[0];
    const float* R     = (const float*)d_in[1];
    const float* f0    = (const float*)d_in[2];
    const float* f1    = (const float*)d_in[3];
    const float* f2    = (const float*)d_in[4];
    const float* f3    = (const float*)d_in[5];
    const float* bnr_g = (const float*)d_in[6];
    const float* bnr_b = (const float*)d_in[7];
    const float* bne_g = (const float*)d_in[8];
    const float* bne_b = (const float*)d_in[9];
    const float* bnw_g = (const float*)d_in[10];
    const float* bnw_b = (const float*)d_in[11];
    const int*   r_idx = (const int*)d_in[12];
    const int*   e_idx1 = (const int*)d_in[13];
    const int*   e_idx2 = (const int*)d_in[14];

    float* outPred = (float*)d_out;                   // [128, 10000]
    float* outW    = outPred + (size_t)BATCH * NENT;  // [100^4]

    // --- build bf16 3-segment GEMM operands ---
    pair_contract<<<MN, 256>>>(f0, f1, 0);   // Abig [hi|hi|lo]
    pair_contract<<<MN, 256>>>(f2, f3, 1);   // Bbig [hi|lo|hi]

    // --- prediction path (cheap, fp32) ---
    bn_kernel<<<DR, 128>>>(R, r_idx,  bnr_g, bnr_b, DR, 0);
    bn_kernel<<<DE, 128>>>(E, e_idx1, bne_g, bne_b, DE, 1);
    bn_kernel<<<DE, 128>>>(E, e_idx2, bne_g, bne_b, DE, 2);
    tr_wout_kernel<<<BATCH, 256>>>(f0, f1, f2, f3);
    bn_kernel<<<DE, 128>>>(nullptr, nullptr, bnw_g, bnw_b, DE, 3);
    scores_kernel<<<BATCH, 256>>>(E);
    softmax_kernel<<<BATCH, 256>>>(outPred);

    // --- W = Abig @ Bbig^T via mma.sync bf16 (fp32-quality, fp32 accum) ---
    static int smem_set = 0;
    if (!smem_set) {
        cudaFuncSetAttribute(tn_gemm, cudaFuncAttributeMaxDynamicSharedMemorySize, SMEM_TOTAL);
        smem_set = 1;
    }
    dim3 grid((MN + BN - 1) / BN, (MN + BM - 1) / BM);   // 40 x 79
    tn_gemm<<<grid, 256, SMEM_TOTAL>>>(outW);
}

// round 5
// speedup vs baseline: 3.1835x; 1.3318x over previous
#include <cuda_runtime.h>
#include <cuda_fp16.h>
#include <math.h>
#include <stdint.h>

#define DE    100
#define DR    100
#define RK    40
#define NENT  10000
#define BATCH 128
#define KDIM  1600          // RK*RK
#define MN    10000         // DE*DE
#define FSTR  (DE*RK)       // 4000
#define KBIG  3200          // [hi|lo] / [hi|hi] concatenated K (fp16)
#define BKC   64            // fp16 per K-chunk (128 B row)
#define NCHUNK (KBIG/BKC)   // 50
#define NSTG  3

// GEMM tile
#define BM 128
#define BN 256
#define STAGE_A (BM*128)              // 16384 B
#define STAGE_B (BN*128)              // 32768 B
#define STAGE_BYTES (STAGE_A+STAGE_B) // 49152 B
#define SMEM_TOTAL (NSTG*STAGE_BYTES) // 147456 B

// ---------- device scratch ----------
__device__ __half g_Abig[(size_t)MN * KBIG];  // 64 MB  [hi|lo]
__device__ __half g_Bbig[(size_t)MN * KBIG];  // 64 MB  [hi|hi]
__device__ float g_rbn  [BATCH * DR];
__device__ float g_e1bn [BATCH * DE];
__device__ float g_e2bn [BATCH * DE];
__device__ float g_wout [BATCH * DE];
__device__ float g_woutbn[BATCH * DE];
__device__ float g_scores[BATCH * NENT];

// ==================== helpers ====================
__device__ __forceinline__ uint32_t smem_u32(const void* p) {
    uint32_t a;
    asm("{ .reg .u64 t; cvta.to.shared.u64 t, %1; cvt.u32.u64 %0, t; }" : "=r"(a) : "l"(p));
    return a;
}
__device__ __forceinline__ void cp16(uint32_t dst, const void* src) {
    asm volatile("cp.async.cg.shared.global [%0], [%1], 16;\n" :: "r"(dst), "l"(src) : "memory");
}
__device__ __forceinline__ void cp_commit() {
    asm volatile("cp.async.commit_group;" ::: "memory");
}
template <int N>
__device__ __forceinline__ void cp_wait() {
    asm volatile("cp.async.wait_group %0;" :: "n"(N) : "memory");
}
__device__ __forceinline__ void ldsm_x4(uint32_t& r0, uint32_t& r1, uint32_t& r2, uint32_t& r3, uint32_t addr) {
    asm volatile("ldmatrix.sync.aligned.m8n8.x4.shared.b16 {%0,%1,%2,%3}, [%4];"
                 : "=r"(r0), "=r"(r1), "=r"(r2), "=r"(r3) : "r"(addr));
}
__device__ __forceinline__ void mma16816(float* c, const uint32_t* a, uint32_t b0, uint32_t b1) {
    asm volatile(
        "mma.sync.aligned.m16n8k16.row.col.f32.f16.f16.f32 "
        "{%0,%1,%2,%3}, {%4,%5,%6,%7}, {%8,%9}, {%0,%1,%2,%3};"
        : "+f"(c[0]), "+f"(c[1]), "+f"(c[2]), "+f"(c[3])
        : "r"(a[0]), "r"(a[1]), "r"(a[2]), "r"(a[3]), "r"(b0), "r"(b1));
}

// ---------------------------------------------------------------------
// Amat / CmatT construction -> fp16 hi/lo, 2-segment K concatenation.
//   Abig row = [hi | lo]     Bbig row = [hi | hi]
// segment-wise TN dot = hi_a.hi_b + lo_a.hi_b = (a to 22 bits).hi_b
// dropped term a.lo_b <= 2^-11 relative (~3e-4 observed scale).
// swap==0: val[(p,q)][a*40+c] = sum_b f0[a,p,b] f1[b,q,c]   (Abig)
// swap==1: val[(p,q)][a*40+c] = sum_b f2[c,p,b] f3[b,q,a]   (Bbig)
__global__ __launch_bounds__(256) void pair_contract(const float* __restrict__ X,
                                                     const float* __restrict__ Y,
                                                     int swap)
{
    __shared__ float Xs[RK][RK + 1];
    __shared__ float Ys[RK][RK + 1];
    __half* out = swap ? g_Bbig : g_Abig;
    const int p = blockIdx.x / DE;
    const int q = blockIdx.x % DE;
    const int t = threadIdx.x;

    for (int lin = t; lin < RK * RK; lin += 256) {
        int u = lin / RK, w = lin % RK;
        Xs[u][w] = X[u * FSTR + p * RK + w];
        Ys[u][w] = Y[u * FSTR + q * RK + w];
    }
    __syncthreads();

    for (int lin = t; lin < RK * RK; lin += 256) {
        int a = lin / RK, c = lin % RK;
        int uu = swap ? c : a;
        int vv = swap ? a : c;
        float s = 0.f;
#pragma unroll
        for (int b = 0; b < RK; b++) s += Xs[uu][b] * Ys[b][vv];
        __half hi = __float2half(s);
        size_t rb = (size_t)blockIdx.x * KBIG;
        out[rb + lin] = hi;
        if (swap == 0) {            // A: [hi | lo]
            out[rb + KDIM + lin] = __float2half(s - __half2float(hi));
        } else {                    // B: [hi | hi]
            out[rb + KDIM + lin] = hi;
        }
    }
}

// ---------------------------------------------------------------------
// W[10000,10000] = Abig @ Bbig^T over K=3200 fp16, fp32 accum.
// mma.sync.m16n8k16 + ldmatrix + 3-stage cp.async. CTA tile 128x256.
// 8 warps as 2(m) x 4(n); warp tile 64x64.
__global__ void __launch_bounds__(256, 1) tn_gemm(float* __restrict__ Wout)
{
    extern __shared__ __align__(1024) char smem[];
    const uint32_t sb = smem_u32(smem);
    const int tid  = threadIdx.x;
    const int lane = tid & 31;
    const int wid  = tid >> 5;
    const int wm   = wid >> 2;       // 0..1
    const int wn   = wid & 3;        // 0..3
    const int m0 = blockIdx.y * BM;
    const int n0 = blockIdx.x * BN;
    const __half* __restrict__ A = g_Abig;
    const __half* __restrict__ B = g_Bbig;

    float acc[4][8][4];
#pragma unroll
    for (int i = 0; i < 4; i++)
#pragma unroll
        for (int j = 0; j < 8; j++)
#pragma unroll
            for (int k = 0; k < 4; k++) acc[i][j][k] = 0.f;

    // ---- cp.async stage fill ----
    auto load_stage = [&](int ck, int stg) {
        uint32_t sA = sb + stg * STAGE_BYTES;
        uint32_t sB = sA + STAGE_A;
#pragma unroll
        for (int i = 0; i < 4; i++) {          // A: 1024 chunks of 16B
            int q = tid + i * 256;
            int row = q >> 3, seg = q & 7;
            int gm = m0 + row; if (gm > MN - 1) gm = MN - 1;
            const void* src = A + (size_t)gm * KBIG + ck * BKC + seg * 8;
            cp16(sA + row * 128 + ((seg * 16) ^ ((row & 7) << 4)), src);
        }
#pragma unroll
        for (int i = 0; i < 8; i++) {          // B: 2048 chunks
            int q = tid + i * 256;
            int row = q >> 3, seg = q & 7;
            int gn = n0 + row; if (gn > MN - 1) gn = MN - 1;
            const void* src = B + (size_t)gn * KBIG + ck * BKC + seg * 8;
            cp16(sB + row * 128 + ((seg * 16) ^ ((row & 7) << 4)), src);
        }
        cp_commit();
    };

    // ---- per-thread ldmatrix address pieces ----
    const int aq = lane >> 3;
    const int arow = ((aq & 1) << 3) + (lane & 7);      // + wm*64 + mi*16
    const int akb  = (aq >> 1) << 4;                    // 0 | 16
    const int bq = lane >> 3;
    const int brow = ((bq >> 1) << 3) + (lane & 7);     // + wn*64 + ng*16
    const int bkb  = (bq & 1) << 4;
    const int xm = (lane & 7) << 4;                     // swizzle xor mask

    uint32_t aoff[4], boff[4];
#pragma unroll
    for (int mi = 0; mi < 4; mi++) aoff[mi] = (wm * 64 + mi * 16 + arow) * 128;
#pragma unroll
    for (int ng = 0; ng < 4; ng++) boff[ng] = (wn * 64 + ng * 16 + brow) * 128;
    uint32_t kA[4], kB[4];
#pragma unroll
    for (int ks = 0; ks < 4; ks++) {
        kA[ks] = (uint32_t)((ks * 32 + akb) ^ xm);
        kB[ks] = (uint32_t)((ks * 32 + bkb) ^ xm);
    }

    // ---- pipeline prologue ----
    load_stage(0, 0);
    load_stage(1, 1);

    for (int c = 0; c < NCHUNK; c++) {
        // After the final commit (chunk NCHUNK-1, committed at iter NCHUNK-3)
        // there are no more commits, so on the last iteration wait_group<1>
        // would NOT guarantee the final chunk's arrival -> drain fully.
        if (c < NCHUNK - 1) cp_wait<1>(); else cp_wait<0>();
        __syncthreads();
        if (c + 2 < NCHUNK) load_stage(c + 2, (c + 2) % NSTG);

        uint32_t sA = sb + (c % NSTG) * STAGE_BYTES;
        uint32_t sB = sA + STAGE_A;

#pragma unroll
        for (int ks = 0; ks < 4; ks++) {
            uint32_t a[4][4];
#pragma unroll
            for (int mi = 0; mi < 4; mi++)
                ldsm_x4(a[mi][0], a[mi][1], a[mi][2], a[mi][3], sA + aoff[mi] + kA[ks]);
#pragma unroll
            for (int ng = 0; ng < 4; ng++) {
                uint32_t b0, b1, b2, b3;
                ldsm_x4(b0, b1, b2, b3, sB + boff[ng] + kB[ks]);
#pragma unroll
                for (int mi = 0; mi < 4; mi++) {
                    mma16816(acc[mi][ng * 2 + 0], a[mi], b0, b1);
                    mma16816(acc[mi][ng * 2 + 1], a[mi], b2, b3);
                }
            }
        }
        // no trailing __syncthreads needed: next iteration's post-wait barrier
        // orders all reads of stage c before any overwrite of stage c (as c+3).
    }

    // ---- epilogue: register fragments -> gmem ----
    const int rb = m0 + wm * 64 + (lane >> 2);
    const int cb = n0 + wn * 64 + 2 * (lane & 3);
#pragma unroll
    for (int mi = 0; mi < 4; mi++) {
        int r0 = rb + mi * 16;
#pragma unroll
        for (int nj = 0; nj < 8; nj++) {
            int cc = cb + nj * 8;
            if (cc < MN) {
                if (r0 < MN) {
                    float2 v = make_float2(acc[mi][nj][0], acc[mi][nj][1]);
                    *reinterpret_cast<float2*>(Wout + (size_t)r0 * MN + cc) = v;
                }
                if (r0 + 8 < MN) {
                    float2 v = make_float2(acc[mi][nj][2], acc[mi][nj][3]);
                    *reinterpret_cast<float2*>(Wout + (size_t)(r0 + 8) * MN + cc) = v;
                }
            }
        }
    }
}

// ---------------------------------------------------------------------
// BatchNorm1d (training mode, biased variance) over the batch dim.
__global__ __launch_bounds__(128) void bn_kernel(const float* __restrict__ table,
                                                 const int* __restrict__ idx,
                                                 const float* __restrict__ gamma,
                                                 const float* __restrict__ beta,
                                                 int D, int dst_sel)
{
    const int col = blockIdx.x;
    const int b   = threadIdx.x;
    float* out = (dst_sel == 0) ? g_rbn :
                 (dst_sel == 1) ? g_e1bn :
                 (dst_sel == 2) ? g_e2bn : g_woutbn;

    float x;
    if (table) {
        int row = idx[b];
        x = table[(size_t)row * D + col];
    } else {
        x = g_wout[b * D + col];
    }

    __shared__ float ssum[4], ssq[4];
    __shared__ float smu, srs;
    float s = x, sq = x * x;
#pragma unroll
    for (int o = 16; o > 0; o >>= 1) {
        s  += __shfl_down_sync(0xffffffffu, s, o);
        sq += __shfl_down_sync(0xffffffffu, sq, o);
    }
    int w = b >> 5, l = b & 31;
    if (l == 0) { ssum[w] = s; ssq[w] = sq; }
    __syncthreads();
    if (b == 0) {
        float ts = ssum[0] + ssum[1] + ssum[2] + ssum[3];
        float tq = ssq[0]  + ssq[1]  + ssq[2]  + ssq[3];
        float mu  = ts * (1.f / BATCH);
        float var = tq * (1.f / BATCH) - mu * mu;
        smu = mu;
        srs = rsqrtf(var + 1e-5f);
    }
    __syncthreads();
    out[b * D + col] = gamma[col] * (x - smu) * srs + beta[col];
}

// ---------------------------------------------------------------------
// Fused per-batch TR contraction for W_out (skips the 512 MB W_mat).
__global__ __launch_bounds__(256) void tr_wout_kernel(const float* __restrict__ f0,
                                                      const float* __restrict__ f1,
                                                      const float* __restrict__ f2,
                                                      const float* __restrict__ f3)
{
    const int bt = blockIdx.x;
    const int t  = threadIdx.x;
    __shared__ float rv[DR], e1v[DE], e2v[DE];
    __shared__ float u0[KDIM], v1[KDIM], v3[KDIM], m2[KDIM], q2[KDIM];

    if (t < DR) rv[t]  = g_rbn [bt * DR + t];
    if (t < DE) { e1v[t] = g_e1bn[bt * DE + t]; e2v[t] = g_e2bn[bt * DE + t]; }
    __syncthreads();

    for (int lin = t; lin < KDIM; lin += 256) {
        int u = lin / RK, w = lin % RK;
        float s0 = 0.f, s1 = 0.f, s3 = 0.f;
        for (int r = 0; r < DR; r++) {
            s0 += rv[r]  * f0[u * FSTR + r * RK + w];
            s1 += e1v[r] * f1[u * FSTR + r * RK + w];
            s3 += e2v[r] * f3[u * FSTR + r * RK + w];
        }
        u0[lin] = s0; v1[lin] = s1; v3[lin] = s3;
    }
    __syncthreads();

    for (int lin = t; lin < KDIM; lin += 256) {
        int a = lin / RK, c = lin % RK;
        float s = 0.f;
#pragma unroll
        for (int b = 0; b < RK; b++) s += u0[a * RK + b] * v1[b * RK + c];
        m2[lin] = s;
    }
    __syncthreads();

    for (int lin = t; lin < KDIM; lin += 256) {
        int c = lin / RK, d = lin % RK;
        float s = 0.f;
#pragma unroll
        for (int a = 0; a < RK; a++) s += m2[a * RK + c] * v3[d * RK + a];
        q2[lin] = s;
    }
    __syncthreads();

    if (t < DE) {
        float s = 0.f;
        for (int c = 0; c < RK; c++) {
            const float* f2row = f2 + c * FSTR + t * RK;
#pragma unroll
            for (int d = 0; d < RK; d++) s += q2[c * RK + d] * f2row[d];
        }
        g_wout[bt * DE + t] = s;
    }
}

// ---------------------------------------------------------------------
__global__ __launch_bounds__(256) void scores_kernel(const float* __restrict__ E)
{
    const int bt = blockIdx.x;
    const int t  = threadIdx.x;
    __shared__ float wv[DE];
    if (t < DE) wv[t] = g_woutbn[bt * DE + t];
    __syncthreads();
    for (int e = t; e < NENT; e += 256) {
        const float* er = E + (size_t)e * DE;
        float s = 0.f;
#pragma unroll 4
        for (int i = 0; i < DE; i++) s += wv[i] * er[i];
        g_scores[(size_t)bt * NENT + e] = s;
    }
}

// ---------------------------------------------------------------------
__global__ __launch_bounds__(256) void softmax_kernel(float* __restrict__ pred)
{
    const int bt = blockIdx.x;
    const int t  = threadIdx.x;
    const float* row = g_scores + (size_t)bt * NENT;
    __shared__ float red[8];
    __shared__ float smx, ssumv;

    float mx = -1e30f;
    for (int e = t; e < NENT; e += 256) mx = fmaxf(mx, row[e]);
#pragma unroll
    for (int o = 16; o > 0; o >>= 1) mx = fmaxf(mx, __shfl_xor_sync(0xffffffffu, mx, o));
    if ((t & 31) == 0) red[t >> 5] = mx;
    __syncthreads();
    if (t == 0) {
        float m = red[0];
        for (int i = 1; i < 8; i++) m = fmaxf(m, red[i]);
        smx = m;
    }
    __syncthreads();
    mx = smx;

    float sum = 0.f;
    for (int e = t; e < NENT; e += 256) sum += expf(row[e] - mx);
#pragma unroll
    for (int o = 16; o > 0; o >>= 1) sum += __shfl_xor_sync(0xffffffffu, sum, o);
    __syncthreads();
    if ((t & 31) == 0) red[t >> 5] = sum;
    __syncthreads();
    if (t == 0) {
        float s = 0.f;
        for (int i = 0; i < 8; i++) s += red[i];
        ssumv = s;
    }
    __syncthreads();
    const float inv = 1.f / ssumv;
    for (int e = t; e < NENT; e += 256)
        pred[(size_t)bt * NENT + e] = expf(row[e] - mx) * inv;
}

// ---------------------------------------------------------------------
extern "C" void kernel_launch(void* const* d_in, const int* in_sizes, int n_in,
                              void* d_out, int out_size)
{
    const float* E     = (const float*)d_in[0];
    const float* R     = (const float*)d_in[1];
    const float* f0    = (const float*)d_in[2];
    const float* f1    = (const float*)d_in[3];
    const float* f2    = (const float*)d_in[4];
    const float* f3    = (const float*)d_in[5];
    const float* bnr_g = (const float*)d_in[6];
    const float* bnr_b = (const float*)d_in[7];
    const float* bne_g = (const float*)d_in[8];
    const float* bne_b = (const float*)d_in[9];
    const float* bnw_g = (const float*)d_in[10];
    const float* bnw_b = (const float*)d_in[11];
    const int*   r_idx = (const int*)d_in[12];
    const int*   e_idx1 = (const int*)d_in[13];
    const int*   e_idx2 = (const int*)d_in[14];

    float* outPred = (float*)d_out;                   // [128, 10000]
    float* outW    = outPred + (size_t)BATCH * NENT;  // [100^4]

    // --- build fp16 2-segment GEMM operands ---
    pair_contract<<<MN, 256>>>(f0, f1, 0);   // Abig [hi|lo]
    pair_contract<<<MN, 256>>>(f2, f3, 1);   // Bbig [hi|hi]

    // --- prediction path (cheap, fp32) ---
    bn_kernel<<<DR, 128>>>(R, r_idx,  bnr_g, bnr_b, DR, 0);
    bn_kernel<<<DE, 128>>>(E, e_idx1, bne_g, bne_b, DE, 1);
    bn_kernel<<<DE, 128>>>(E, e_idx2, bne_g, bne_b, DE, 2);
    tr_wout_kernel<<<BATCH, 256>>>(f0, f1, f2, f3);
    bn_kernel<<<DE, 128>>>(nullptr, nullptr, bnw_g, bnw_b, DE, 3);
    scores_kernel<<<BATCH, 256>>>(E);
    softmax_kernel<<<BATCH, 256>>>(outPred);

    // --- W = Abig @ Bbig^T via mma.sync fp16 (22-bit A x 11-bit B, fp32 accum) ---
    cudaFuncSetAttribute(tn_gemm, cudaFuncAttributeMaxDynamicSharedMemorySize, SMEM_TOTAL);
    dim3 grid((MN + BN - 1) / BN, (MN + BM - 1) / BM);   // 40 x 79
    tn_gemm<<<grid, 256, SMEM_TOTAL>>>(outW);
}

// round 7
// speedup vs baseline: 4.6654x; 1.4655x over previous
#include <cuda_runtime.h>
#include <cuda_fp16.h>
#include <math.h>
#include <stdint.h>

#define DE    100
#define DR    100
#define RK    40
#define NENT  10000
#define BATCH 128
#define KDIM  1600          // RK*RK — single-segment fp16 K
#define MN    10000         // DE*DE
#define FSTR  (DE*RK)       // 4000
#define KBIG  1600
#define BKC   64            // fp16 per K-chunk (128 B row)
#define NCHUNK (KBIG/BKC)   // 25
#define NSTG  3

// GEMM tile
#define BM 128
#define BN 256
#define STAGE_A (BM*128)              // 16384 B
#define STAGE_B (BN*128)              // 32768 B
#define STAGE_BYTES (STAGE_A+STAGE_B) // 49152 B
#define SMEM_TOTAL (NSTG*STAGE_BYTES) // 147456 B

// ---------- device scratch ----------
__device__ __half g_Abig[(size_t)MN * KBIG];  // 32 MB
__device__ __half g_Bbig[(size_t)MN * KBIG];  // 32 MB
__device__ float g_rbn  [BATCH * DR];
__device__ float g_e1bn [BATCH * DE];
__device__ float g_e2bn [BATCH * DE];
__device__ float g_wout [BATCH * DE];
__device__ float g_woutbn[BATCH * DE];
__device__ float g_scores[BATCH * NENT];

// ==================== helpers ====================
__device__ __forceinline__ uint32_t smem_u32(const void* p) {
    uint32_t a;
    asm("{ .reg .u64 t; cvta.to.shared.u64 t, %1; cvt.u32.u64 %0, t; }" : "=r"(a) : "l"(p));
    return a;
}
__device__ __forceinline__ void cp16(uint32_t dst, const void* src) {
    asm volatile("cp.async.cg.shared.global [%0], [%1], 16;\n" :: "r"(dst), "l"(src) : "memory");
}
__device__ __forceinline__ void cp_commit() {
    asm volatile("cp.async.commit_group;" ::: "memory");
}
template <int N>
__device__ __forceinline__ void cp_wait() {
    asm volatile("cp.async.wait_group %0;" :: "n"(N) : "memory");
}
__device__ __forceinline__ void ldsm_x4(uint32_t& r0, uint32_t& r1, uint32_t& r2, uint32_t& r3, uint32_t addr) {
    asm volatile("ldmatrix.sync.aligned.m8n8.x4.shared.b16 {%0,%1,%2,%3}, [%4];"
                 : "=r"(r0), "=r"(r1), "=r"(r2), "=r"(r3) : "r"(addr));
}
__device__ __forceinline__ void mma16816(float* c, const uint32_t* a, uint32_t b0, uint32_t b1) {
    asm volatile(
        "mma.sync.aligned.m16n8k16.row.col.f32.f16.f16.f32 "
        "{%0,%1,%2,%3}, {%4,%5,%6,%7}, {%8,%9}, {%0,%1,%2,%3};"
        : "+f"(c[0]), "+f"(c[1]), "+f"(c[2]), "+f"(c[3])
        : "r"(a[0]), "r"(a[1]), "r"(a[2]), "r"(a[3]), "r"(b0), "r"(b1));
}

// ---------------------------------------------------------------------
// Amat / CmatT construction -> fp16 RN (single segment).
// Error model (HW-calibrated rounds 3/5): per dropped term 0.85*half-ulp;
// here two terms ~2^-12 each -> rel_err(W) ~ 2.9e-4 << 1e-3.
// swap==0: val[(p,q)][a*40+c] = sum_b f0[a,p,b] f1[b,q,c]   (Abig)
// swap==1: val[(p,q)][a*40+c] = sum_b f2[c,p,b] f3[b,q,a]   (Bbig)
__global__ __launch_bounds__(256) void pair_contract(const float* __restrict__ X,
                                                     const float* __restrict__ Y,
                                                     int swap)
{
    __shared__ float Xs[RK][RK + 1];
    __shared__ float Ys[RK][RK + 1];
    __half* out = swap ? g_Bbig : g_Abig;
    const int p = blockIdx.x / DE;
    const int q = blockIdx.x % DE;
    const int t = threadIdx.x;

    for (int lin = t; lin < RK * RK; lin += 256) {
        int u = lin / RK, w = lin % RK;
        Xs[u][w] = X[u * FSTR + p * RK + w];
        Ys[u][w] = Y[u * FSTR + q * RK + w];
    }
    __syncthreads();

    for (int lin = t; lin < RK * RK; lin += 256) {
        int a = lin / RK, c = lin % RK;
        int uu = swap ? c : a;
        int vv = swap ? a : c;
        float s = 0.f;
#pragma unroll
        for (int b = 0; b < RK; b++) s += Xs[uu][b] * Ys[b][vv];
        out[(size_t)blockIdx.x * KBIG + lin] = __float2half(s);
    }
}

// ---------------------------------------------------------------------
// W[10000,10000] = Abig @ Bbig^T over K=1600 fp16, fp32 accum.
// mma.sync.m16n8k16 + ldmatrix + 3-stage cp.async. CTA tile 128x256.
// 8 warps as 2(m) x 4(n); warp tile 64x64.
__global__ void __launch_bounds__(256, 1) tn_gemm(float* __restrict__ Wout)
{
    extern __shared__ __align__(1024) char smem[];
    const uint32_t sb = smem_u32(smem);
    const int tid  = threadIdx.x;
    const int lane = tid & 31;
    const int wid  = tid >> 5;
    const int wm   = wid >> 2;       // 0..1
    const int wn   = wid & 3;        // 0..3
    const int m0 = blockIdx.y * BM;
    const int n0 = blockIdx.x * BN;
    const __half* __restrict__ A = g_Abig;
    const __half* __restrict__ B = g_Bbig;

    float acc[4][8][4];
#pragma unroll
    for (int i = 0; i < 4; i++)
#pragma unroll
        for (int j = 0; j < 8; j++)
#pragma unroll
            for (int k = 0; k < 4; k++) acc[i][j][k] = 0.f;

    // ---- cp.async stage fill ----
    auto load_stage = [&](int ck, int stg) {
        uint32_t sA = sb + stg * STAGE_BYTES;
        uint32_t sB = sA + STAGE_A;
#pragma unroll
        for (int i = 0; i < 4; i++) {          // A: 1024 chunks of 16B
            int q = tid + i * 256;
            int row = q >> 3, seg = q & 7;
            int gm = m0 + row; if (gm > MN - 1) gm = MN - 1;
            const void* src = A + (size_t)gm * KBIG + ck * BKC + seg * 8;
            cp16(sA + row * 128 + ((seg * 16) ^ ((row & 7) << 4)), src);
        }
#pragma unroll
        for (int i = 0; i < 8; i++) {          // B: 2048 chunks
            int q = tid + i * 256;
            int row = q >> 3, seg = q & 7;
            int gn = n0 + row; if (gn > MN - 1) gn = MN - 1;
            const void* src = B + (size_t)gn * KBIG + ck * BKC + seg * 8;
            cp16(sB + row * 128 + ((seg * 16) ^ ((row & 7) << 4)), src);
        }
        cp_commit();
    };

    // ---- per-thread ldmatrix address pieces ----
    const int aq = lane >> 3;
    const int arow = ((aq & 1) << 3) + (lane & 7);      // + wm*64 + mi*16
    const int akb  = (aq >> 1) << 4;                    // 0 | 16
    const int bq = lane >> 3;
    const int brow = ((bq >> 1) << 3) + (lane & 7);     // + wn*64 + ng*16
    const int bkb  = (bq & 1) << 4;
    const int xm = (lane & 7) << 4;                     // swizzle xor mask

    uint32_t aoff[4], boff[4];
#pragma unroll
    for (int mi = 0; mi < 4; mi++) aoff[mi] = (wm * 64 + mi * 16 + arow) * 128;
#pragma unroll
    for (int ng = 0; ng < 4; ng++) boff[ng] = (wn * 64 + ng * 16 + brow) * 128;
    uint32_t kA[4], kB[4];
#pragma unroll
    for (int ks = 0; ks < 4; ks++) {
        kA[ks] = (uint32_t)((ks * 32 + akb) ^ xm);
        kB[ks] = (uint32_t)((ks * 32 + bkb) ^ xm);
    }

    // ---- pipeline prologue ----
    load_stage(0, 0);
    load_stage(1, 1);

    for (int c = 0; c < NCHUNK; c++) {
        // After the final commit there are no more commits, so on the last
        // iteration wait_group<1> would not cover the final chunk -> drain.
        if (c < NCHUNK - 1) cp_wait<1>(); else cp_wait<0>();
        __syncthreads();
        if (c + 2 < NCHUNK) load_stage(c + 2, (c + 2) % NSTG);

        uint32_t sA = sb + (c % NSTG) * STAGE_BYTES;
        uint32_t sB = sA + STAGE_A;

#pragma unroll
        for (int ks = 0; ks < 4; ks++) {
            uint32_t a[4][4];
#pragma unroll
            for (int mi = 0; mi < 4; mi++)
                ldsm_x4(a[mi][0], a[mi][1], a[mi][2], a[mi][3], sA + aoff[mi] + kA[ks]);
#pragma unroll
            for (int ng = 0; ng < 4; ng++) {
                uint32_t b0, b1, b2, b3;
                ldsm_x4(b0, b1, b2, b3, sB + boff[ng] + kB[ks]);
#pragma unroll
                for (int mi = 0; mi < 4; mi++) {
                    mma16816(acc[mi][ng * 2 + 0], a[mi], b0, b1);
                    mma16816(acc[mi][ng * 2 + 1], a[mi], b2, b3);
                }
            }
        }
        // trailing sync elided: next iteration's post-wait barrier orders
        // all reads of stage c before any overwrite of stage c (as c+3).
    }

    // ---- epilogue: register fragments -> gmem ----
    const int rb = m0 + wm * 64 + (lane >> 2);
    const int cb = n0 + wn * 64 + 2 * (lane & 3);
#pragma unroll
    for (int mi = 0; mi < 4; mi++) {
        int r0 = rb + mi * 16;
#pragma unroll
        for (int nj = 0; nj < 8; nj++) {
            int cc = cb + nj * 8;
            if (cc < MN) {
                if (r0 < MN) {
                    float2 v = make_float2(acc[mi][nj][0], acc[mi][nj][1]);
                    *reinterpret_cast<float2*>(Wout + (size_t)r0 * MN + cc) = v;
                }
                if (r0 + 8 < MN) {
                    float2 v = make_float2(acc[mi][nj][2], acc[mi][nj][3]);
                    *reinterpret_cast<float2*>(Wout + (size_t)(r0 + 8) * MN + cc) = v;
                }
            }
        }
    }
}

// ---------------------------------------------------------------------
// BatchNorm1d (training mode, biased variance) over the batch dim.
__global__ __launch_bounds__(128) void bn_kernel(const float* __restrict__ table,
                                                 const int* __restrict__ idx,
                                                 const float* __restrict__ gamma,
                                                 const float* __restrict__ beta,
                                                 int D, int dst_sel)
{
    const int col = blockIdx.x;
    const int b   = threadIdx.x;
    float* out = (dst_sel == 0) ? g_rbn :
                 (dst_sel == 1) ? g_e1bn :
                 (dst_sel == 2) ? g_e2bn : g_woutbn;

    float x;
    if (table) {
        int row = idx[b];
        x = table[(size_t)row * D + col];
    } else {
        x = g_wout[b * D + col];
    }

    __shared__ float ssum[4], ssq[4];
    __shared__ float smu, srs;
    float s = x, sq = x * x;
#pragma unroll
    for (int o = 16; o > 0; o >>= 1) {
        s  += __shfl_down_sync(0xffffffffu, s, o);
        sq += __shfl_down_sync(0xffffffffu, sq, o);
    }
    int w = b >> 5, l = b & 31;
    if (l == 0) { ssum[w] = s; ssq[w] = sq; }
    __syncthreads();
    if (b == 0) {
        float ts = ssum[0] + ssum[1] + ssum[2] + ssum[3];
        float tq = ssq[0]  + ssq[1]  + ssq[2]  + ssq[3];
        float mu  = ts * (1.f / BATCH);
        float var = tq * (1.f / BATCH) - mu * mu;
        smu = mu;
        srs = rsqrtf(var + 1e-5f);
    }
    __syncthreads();
    out[b * D + col] = gamma[col] * (x - smu) * srs + beta[col];
}

// ---------------------------------------------------------------------
// Fused per-batch TR contraction for W_out (skips the 512 MB W_mat).
__global__ __launch_bounds__(256) void tr_wout_kernel(const float* __restrict__ f0,
                                                      const float* __restrict__ f1,
                                                      const float* __restrict__ f2,
                                                      const float* __restrict__ f3)
{
    const int bt = blockIdx.x;
    const int t  = threadIdx.x;
    __shared__ float rv[DR], e1v[DE], e2v[DE];
    __shared__ float u0[KDIM], v1[KDIM], v3[KDIM], m2[KDIM], q2[KDIM];

    if (t < DR) rv[t]  = g_rbn [bt * DR + t];
    if (t < DE) { e1v[t] = g_e1bn[bt * DE + t]; e2v[t] = g_e2bn[bt * DE + t]; }
    __syncthreads();

    for (int lin = t; lin < KDIM; lin += 256) {
        int u = lin / RK, w = lin % RK;
        float s0 = 0.f, s1 = 0.f, s3 = 0.f;
        for (int r = 0; r < DR; r++) {
            s0 += rv[r]  * f0[u * FSTR + r * RK + w];
            s1 += e1v[r] * f1[u * FSTR + r * RK + w];
            s3 += e2v[r] * f3[u * FSTR + r * RK + w];
        }
        u0[lin] = s0; v1[lin] = s1; v3[lin] = s3;
    }
    __syncthreads();

    for (int lin = t; lin < KDIM; lin += 256) {
        int a = lin / RK, c = lin % RK;
        float s = 0.f;
#pragma unroll
        for (int b = 0; b < RK; b++) s += u0[a * RK + b] * v1[b * RK + c];
        m2[lin] = s;
    }
    __syncthreads();

    for (int lin = t; lin < KDIM; lin += 256) {
        int c = lin / RK, d = lin % RK;
        float s = 0.f;
#pragma unroll
        for (int a = 0; a < RK; a++) s += m2[a * RK + c] * v3[d * RK + a];
        q2[lin] = s;
    }
    __syncthreads();

    if (t < DE) {
        float s = 0.f;
        for (int c = 0; c < RK; c++) {
            const float* f2row = f2 + c * FSTR + t * RK;
#pragma unroll
            for (int d = 0; d < RK; d++) s += q2[c * RK + d] * f2row[d];
        }
        g_wout[bt * DE + t] = s;
    }
}

// ---------------------------------------------------------------------
__global__ __launch_bounds__(256) void scores_kernel(const float* __restrict__ E)
{
    const int bt = blockIdx.x;
    const int t  = threadIdx.x;
    __shared__ float wv[DE];
    if (t < DE) wv[t] = g_woutbn[bt * DE + t];
    __syncthreads();
    for (int e = t; e < NENT; e += 256) {
        const float* er = E + (size_t)e * DE;
        float s = 0.f;
#pragma unroll 4
        for (int i = 0; i < DE; i++) s += wv[i] * er[i];
        g_scores[(size_t)bt * NENT + e] = s;
    }
}

// ---------------------------------------------------------------------
__global__ __launch_bounds__(256) void softmax_kernel(float* __restrict__ pred)
{
    const int bt = blockIdx.x;
    const int t  = threadIdx.x;
    const float* row = g_scores + (size_t)bt * NENT;
    __shared__ float red[8];
    __shared__ float smx, ssumv;

    float mx = -1e30f;
    for (int e = t; e < NENT; e += 256) mx = fmaxf(mx, row[e]);
#pragma unroll
    for (int o = 16; o > 0; o >>= 1) mx = fmaxf(mx, __shfl_xor_sync(0xffffffffu, mx, o));
    if ((t & 31) == 0) red[t >> 5] = mx;
    __syncthreads();
    if (t == 0) {
        float m = red[0];
        for (int i = 1; i < 8; i++) m = fmaxf(m, red[i]);
        smx = m;
    }
    __syncthreads();
    mx = smx;

    float sum = 0.f;
    for (int e = t; e < NENT; e += 256) sum += expf(row[e] - mx);
#pragma unroll
    for (int o = 16; o > 0; o >>= 1) sum += __shfl_xor_sync(0xffffffffu, sum, o);
    __syncthreads();
    if ((t & 31) == 0) red[t >> 5] = sum;
    __syncthreads();
    if (t == 0) {
        float s = 0.f;
        for (int i = 0; i < 8; i++) s += red[i];
        ssumv = s;
    }
    __syncthreads();
    const float inv = 1.f / ssumv;
    for (int e = t; e < NENT; e += 256)
        pred[(size_t)bt * NENT + e] = expf(row[e] - mx) * inv;
}

// ---------------------------------------------------------------------
extern "C" void kernel_launch(void* const* d_in, const int* in_sizes, int n_in,
                              void* d_out, int out_size)
{
    const float* E     = (const float*)d_in[0];
    const float* R     = (const float*)d_in[1];
    const float* f0    = (const float*)d_in[2];
    const float* f1    = (const float*)d_in[3];
    const float* f2    = (const float*)d_in[4];
    const float* f3    = (const float*)d_in[5];
    const float* bnr_g = (const float*)d_in[6];
    const float* bnr_b = (const float*)d_in[7];
    const float* bne_g = (const float*)d_in[8];
    const float* bne_b = (const float*)d_in[9];
    const float* bnw_g = (const float*)d_in[10];
    const float* bnw_b = (const float*)d_in[11];
    const int*   r_idx = (const int*)d_in[12];
    const int*   e_idx1 = (const int*)d_in[13];
    const int*   e_idx2 = (const int*)d_in[14];

    float* outPred = (float*)d_out;                   // [128, 10000]
    float* outW    = outPred + (size_t)BATCH * NENT;  // [100^4]

    // --- build fp16 GEMM operands (single segment, K=1600) ---
    pair_contract<<<MN, 256>>>(f0, f1, 0);   // Abig
    pair_contract<<<MN, 256>>>(f2, f3, 1);   // Bbig

    // --- prediction path (cheap, fp32) ---
    bn_kernel<<<DR, 128>>>(R, r_idx,  bnr_g, bnr_b, DR, 0);
    bn_kernel<<<DE, 128>>>(E, e_idx1, bne_g, bne_b, DE, 1);
    bn_kernel<<<DE, 128>>>(E, e_idx2, bne_g, bne_b, DE, 2);
    tr_wout_kernel<<<BATCH, 256>>>(f0, f1, f2, f3);
    bn_kernel<<<DE, 128>>>(nullptr, nullptr, bnw_g, bnw_b, DE, 3);
    scores_kernel<<<BATCH, 256>>>(E);
    softmax_kernel<<<BATCH, 256>>>(outPred);

    // --- W = Abig @ Bbig^T via mma.sync fp16 (fp32 accum) ---
    cudaFuncSetAttribute(tn_gemm, cudaFuncAttributeMaxDynamicSharedMemorySize, SMEM_TOTAL);
    dim3 grid((MN + BN - 1) / BN, (MN + BM - 1) / BM);   // 40 x 79
    tn_gemm<<<grid, 256, SMEM_TOTAL>>>(outW);
}

// round 8
// speedup vs baseline: 7.6110x; 1.6314x over previous
#include <cuda_runtime.h>
#include <cuda_fp16.h>
#include <math.h>
#include <stdint.h>

#define DE    100
#define DR    100
#define RK    40
#define NENT  10000
#define BATCH 128
#define KDIM  1600          // RK*RK — single-segment fp16 K
#define MN    10000         // DE*DE
#define FSTR  (DE*RK)       // 4000
#define KBIG  1600
#define BKC   64            // fp16 per K-chunk (128 B row)
#define NCHUNK (KBIG/BKC)   // 25
#define NSTG  3

// GEMM tile (occ-2 sizing: 64 accum regs/thread)
#define BM 128
#define BN 128
#define STAGE_A (BM*128)              // 16384 B
#define STAGE_B (BN*128)              // 16384 B
#define STAGE_BYTES (STAGE_A+STAGE_B) // 32768 B
#define SMEM_TOTAL (NSTG*STAGE_BYTES) // 98304 B/CTA -> 2 CTAs/SM
#define ERS 136                        // epilogue smem row stride (floats)

// ---------- device scratch ----------
__device__ __half g_Abig[(size_t)MN * KBIG];  // 32 MB
__device__ __half g_Bbig[(size_t)MN * KBIG];  // 32 MB
__device__ float g_rbn  [BATCH * DR];
__device__ float g_e1bn [BATCH * DE];
__device__ float g_e2bn [BATCH * DE];
__device__ float g_wout [BATCH * DE];
__device__ float g_woutbn[BATCH * DE];
__device__ float g_scores[BATCH * NENT];

// ==================== helpers ====================
__device__ __forceinline__ uint32_t smem_u32(const void* p) {
    uint32_t a;
    asm("{ .reg .u64 t; cvta.to.shared.u64 t, %1; cvt.u32.u64 %0, t; }" : "=r"(a) : "l"(p));
    return a;
}
__device__ __forceinline__ void cp16(uint32_t dst, const void* src) {
    asm volatile("cp.async.cg.shared.global [%0], [%1], 16;\n" :: "r"(dst), "l"(src) : "memory");
}
__device__ __forceinline__ void cp_commit() {
    asm volatile("cp.async.commit_group;" ::: "memory");
}
template <int N>
__device__ __forceinline__ void cp_wait() {
    asm volatile("cp.async.wait_group %0;" :: "n"(N) : "memory");
}
__device__ __forceinline__ void ldsm_x4(uint32_t& r0, uint32_t& r1, uint32_t& r2, uint32_t& r3, uint32_t addr) {
    asm volatile("ldmatrix.sync.aligned.m8n8.x4.shared.b16 {%0,%1,%2,%3}, [%4];"
                 : "=r"(r0), "=r"(r1), "=r"(r2), "=r"(r3) : "r"(addr));
}
__device__ __forceinline__ void mma16816(float* c, const uint32_t* a, uint32_t b0, uint32_t b1) {
    asm volatile(
        "mma.sync.aligned.m16n8k16.row.col.f32.f16.f16.f32 "
        "{%0,%1,%2,%3}, {%4,%5,%6,%7}, {%8,%9}, {%0,%1,%2,%3};"
        : "+f"(c[0]), "+f"(c[1]), "+f"(c[2]), "+f"(c[3])
        : "r"(a[0]), "r"(a[1]), "r"(a[2]), "r"(a[3]), "r"(b0), "r"(b1));
}

// ---------------------------------------------------------------------
// pair_contract v2: per (p,q) compute T = Xs(40x40) @ Ys(40x40) with 2x4
// register tiles, then out = swap ? T^T : T (fp16 RN, K=1600 layout).
// swap==0 (Abig): T[a][c] = sum_b f0[a,p,b] f1[b,q,c]
// swap==1 (Bbig): out[a][c] = sum_b f2[c,p,b] f3[b,q,a] = T[c][a]
__global__ __launch_bounds__(256) void pair_contract(const float* __restrict__ X,
                                                     const float* __restrict__ Y,
                                                     int swap)
{
    __shared__ float Xs[RK][44];
    __shared__ float Ys[RK][44];
    __half* out = swap ? g_Bbig : g_Abig;
    const int p = blockIdx.x / DE;
    const int q = blockIdx.x % DE;
    const int t = threadIdx.x;

    for (int lin = t; lin < RK * RK; lin += 256) {
        int u = lin / RK, w = lin % RK;
        Xs[u][w] = X[u * FSTR + p * RK + w];
        Ys[u][w] = Y[u * FSTR + q * RK + w];
    }
    __syncthreads();

    if (t < 200) {
        const int r0 = (t / 10) * 2;    // T row group (2 rows)
        const int s0 = (t % 10) * 4;    // T col group (4 cols)
        float tr[2][4];
#pragma unroll
        for (int i = 0; i < 2; i++)
#pragma unroll
            for (int j = 0; j < 4; j++) tr[i][j] = 0.f;
#pragma unroll
        for (int b = 0; b < RK; b++) {
            float x0 = Xs[r0][b];
            float x1 = Xs[r0 + 1][b];
            float4 y = *reinterpret_cast<const float4*>(&Ys[b][s0]);
            tr[0][0] += x0 * y.x; tr[0][1] += x0 * y.y;
            tr[0][2] += x0 * y.z; tr[0][3] += x0 * y.w;
            tr[1][0] += x1 * y.x; tr[1][1] += x1 * y.y;
            tr[1][2] += x1 * y.z; tr[1][3] += x1 * y.w;
        }
        __half* rb = out + (size_t)blockIdx.x * KBIG;
        if (swap == 0) {
            // rows r0,r0+1 ; cols s0..s0+3 -> two 8B stores
#pragma unroll
            for (int i = 0; i < 2; i++) {
                __half2 h0 = __floats2half2_rn(tr[i][0], tr[i][1]);
                __half2 h1 = __floats2half2_rn(tr[i][2], tr[i][3]);
                uint2 v = make_uint2(*(uint32_t*)&h0, *(uint32_t*)&h1);
                *reinterpret_cast<uint2*>(rb + (r0 + i) * RK + s0) = v;
            }
        } else {
            // out[s0+j][r0..r0+1] = T[r0..r0+1][s0+j] -> four 4B stores
#pragma unroll
            for (int j = 0; j < 4; j++) {
                __half2 h = __floats2half2_rn(tr[0][j], tr[1][j]);
                *reinterpret_cast<__half2*>(rb + (s0 + j) * RK + r0) = h;
            }
        }
    }
}

// ---------------------------------------------------------------------
// W[10000,10000] = Abig @ Bbig^T over K=1600 fp16, fp32 accum.
// CTA tile 128x128, 8 warps (2m x 4n, warp tile 64x32), 3-stage cp.async,
// 2 CTAs/SM, smem-staged coalesced epilogue.
__global__ void __launch_bounds__(256, 2) tn_gemm(float* __restrict__ Wout)
{
    extern __shared__ __align__(1024) char smem[];
    const uint32_t sb = smem_u32(smem);
    const int tid  = threadIdx.x;
    const int lane = tid & 31;
    const int wid  = tid >> 5;
    const int wm   = wid >> 2;       // 0..1
    const int wn   = wid & 3;        // 0..3
    const int m0 = blockIdx.y * BM;
    const int n0 = blockIdx.x * BN;
    const __half* __restrict__ A = g_Abig;
    const __half* __restrict__ B = g_Bbig;

    float acc[4][4][4];
#pragma unroll
    for (int i = 0; i < 4; i++)
#pragma unroll
        for (int j = 0; j < 4; j++)
#pragma unroll
            for (int k = 0; k < 4; k++) acc[i][j][k] = 0.f;

    auto load_stage = [&](int ck, int stg) {
        uint32_t sA = sb + stg * STAGE_BYTES;
        uint32_t sB = sA + STAGE_A;
#pragma unroll
        for (int i = 0; i < 4; i++) {          // A: 1024 chunks of 16B
            int q = tid + i * 256;
            int row = q >> 3, seg = q & 7;
            int gm = m0 + row; if (gm > MN - 1) gm = MN - 1;
            cp16(sA + row * 128 + ((seg * 16) ^ ((row & 7) << 4)),
                 A + (size_t)gm * KBIG + ck * BKC + seg * 8);
        }
#pragma unroll
        for (int i = 0; i < 4; i++) {          // B: 1024 chunks
            int q = tid + i * 256;
            int row = q >> 3, seg = q & 7;
            int gn = n0 + row; if (gn > MN - 1) gn = MN - 1;
            cp16(sB + row * 128 + ((seg * 16) ^ ((row & 7) << 4)),
                 B + (size_t)gn * KBIG + ck * BKC + seg * 8);
        }
        cp_commit();
    };

    // ---- per-thread ldmatrix address pieces ----
    const int aq = lane >> 3;
    const int arow = ((aq & 1) << 3) + (lane & 7);      // + wm*64 + mi*16
    const int akb  = (aq >> 1) << 4;                    // 0 | 16
    const int brow = ((aq >> 1) << 3) + (lane & 7);     // + wn*32 + ng*16
    const int bkb  = (aq & 1) << 4;
    const int xm = (lane & 7) << 4;                     // swizzle xor mask

    uint32_t aoff[4], boff[2];
#pragma unroll
    for (int mi = 0; mi < 4; mi++) aoff[mi] = (wm * 64 + mi * 16 + arow) * 128;
#pragma unroll
    for (int ng = 0; ng < 2; ng++) boff[ng] = (wn * 32 + ng * 16 + brow) * 128;

    load_stage(0, 0);
    load_stage(1, 1);

    for (int c = 0; c < NCHUNK; c++) {
        if (c < NCHUNK - 1) cp_wait<1>(); else cp_wait<0>();
        __syncthreads();
        if (c + 2 < NCHUNK) load_stage(c + 2, (c + 2) % NSTG);

        uint32_t sA = sb + (c % NSTG) * STAGE_BYTES;
        uint32_t sB = sA + STAGE_A;

#pragma unroll
        for (int ks = 0; ks < 4; ks++) {
            const uint32_t kAx = (uint32_t)((ks * 32 + akb) ^ xm);
            const uint32_t kBx = (uint32_t)((ks * 32 + bkb) ^ xm);
            uint32_t a[4][4];
#pragma unroll
            for (int mi = 0; mi < 4; mi++)
                ldsm_x4(a[mi][0], a[mi][1], a[mi][2], a[mi][3], sA + aoff[mi] + kAx);
#pragma unroll
            for (int ng = 0; ng < 2; ng++) {
                uint32_t b0, b1, b2, b3;
                ldsm_x4(b0, b1, b2, b3, sB + boff[ng] + kBx);
#pragma unroll
                for (int mi = 0; mi < 4; mi++) {
                    mma16816(acc[mi][ng * 2 + 0], a[mi], b0, b1);
                    mma16816(acc[mi][ng * 2 + 1], a[mi], b2, b3);
                }
            }
        }
        __syncthreads();   // reads of stage c done before refill next iter
    }

    // ---- epilogue: fragments -> padded smem -> coalesced float4 stores ----
    float* buf = reinterpret_cast<float*>(smem);
    const int rl = wm * 64 + (lane >> 2);
    const int cl = wn * 32 + 2 * (lane & 3);
#pragma unroll
    for (int mi = 0; mi < 4; mi++) {
        int r = rl + mi * 16;
#pragma unroll
        for (int nj = 0; nj < 4; nj++) {
            *reinterpret_cast<float2*>(&buf[r * ERS + cl + nj * 8]) =
                make_float2(acc[mi][nj][0], acc[mi][nj][1]);
            *reinterpret_cast<float2*>(&buf[(r + 8) * ERS + cl + nj * 8]) =
                make_float2(acc[mi][nj][2], acc[mi][nj][3]);
        }
    }
    __syncthreads();
    for (int idx = tid; idx < 128 * 32; idx += 256) {
        int r  = idx >> 5;
        int c4 = (idx & 31) << 2;
        int gm = m0 + r, gn = n0 + c4;
        if (gm < MN && gn < MN) {
            float4 v = make_float4(buf[r * ERS + c4], buf[r * ERS + c4 + 1],
                                   buf[r * ERS + c4 + 2], buf[r * ERS + c4 + 3]);
            *reinterpret_cast<float4*>(Wout + (size_t)gm * MN + gn) = v;
        }
    }
}

// ---------------------------------------------------------------------
// Fused BatchNorm1d for r / e1 / e2 (training mode, biased variance).
__global__ __launch_bounds__(128) void bn3_kernel(const float* __restrict__ R,
                                                  const float* __restrict__ E,
                                                  const int* __restrict__ r_idx,
                                                  const int* __restrict__ e_idx1,
                                                  const int* __restrict__ e_idx2,
                                                  const float* __restrict__ bnr_g,
                                                  const float* __restrict__ bnr_b,
                                                  const float* __restrict__ bne_g,
                                                  const float* __restrict__ bne_b)
{
    const int bid = blockIdx.x;
    const int b   = threadIdx.x;
    const float* table; const int* idx; const float* gamma; const float* beta;
    float* out; int col;
    if (bid < DR)            { table = R; idx = r_idx;  gamma = bnr_g; beta = bnr_b; out = g_rbn;  col = bid; }
    else if (bid < DR + DE)  { table = E; idx = e_idx1; gamma = bne_g; beta = bne_b; out = g_e1bn; col = bid - DR; }
    else                     { table = E; idx = e_idx2; gamma = bne_g; beta = bne_b; out = g_e2bn; col = bid - DR - DE; }

    float x = table[(size_t)idx[b] * DE + col];

    __shared__ float ssum[4], ssq[4];
    __shared__ float smu, srs;
    float s = x, sq = x * x;
#pragma unroll
    for (int o = 16; o > 0; o >>= 1) {
        s  += __shfl_down_sync(0xffffffffu, s, o);
        sq += __shfl_down_sync(0xffffffffu, sq, o);
    }
    int w = b >> 5, l = b & 31;
    if (l == 0) { ssum[w] = s; ssq[w] = sq; }
    __syncthreads();
    if (b == 0) {
        float ts = ssum[0] + ssum[1] + ssum[2] + ssum[3];
        float tq = ssq[0]  + ssq[1]  + ssq[2]  + ssq[3];
        float mu  = ts * (1.f / BATCH);
        float var = tq * (1.f / BATCH) - mu * mu;
        smu = mu;
        srs = rsqrtf(var + 1e-5f);
    }
    __syncthreads();
    out[b * DE + col] = gamma[col] * (x - smu) * srs + beta[col];
}

// ---------------------------------------------------------------------
// BatchNorm for W_out rows (g_wout -> g_woutbn).
__global__ __launch_bounds__(128) void bnw_kernel(const float* __restrict__ gamma,
                                                  const float* __restrict__ beta)
{
    const int col = blockIdx.x;
    const int b   = threadIdx.x;
    float x = g_wout[b * DE + col];

    __shared__ float ssum[4], ssq[4];
    __shared__ float smu, srs;
    float s = x, sq = x * x;
#pragma unroll
    for (int o = 16; o > 0; o >>= 1) {
        s  += __shfl_down_sync(0xffffffffu, s, o);
        sq += __shfl_down_sync(0xffffffffu, sq, o);
    }
    int w = b >> 5, l = b & 31;
    if (l == 0) { ssum[w] = s; ssq[w] = sq; }
    __syncthreads();
    if (b == 0) {
        float ts = ssum[0] + ssum[1] + ssum[2] + ssum[3];
        float tq = ssq[0]  + ssq[1]  + ssq[2]  + ssq[3];
        float mu  = ts * (1.f / BATCH);
        float var = tq * (1.f / BATCH) - mu * mu;
        smu = mu;
        srs = rsqrtf(var + 1e-5f);
    }
    __syncthreads();
    g_woutbn[b * DE + col] = gamma[col] * (x - smu) * srs + beta[col];
}

// ---------------------------------------------------------------------
// Fused per-batch TR contraction for W_out (skips the 512 MB W_mat).
__global__ __launch_bounds__(256) void tr_wout_kernel(const float* __restrict__ f0,
                                                      const float* __restrict__ f1,
                                                      const float* __restrict__ f2,
                                                      const float* __restrict__ f3)
{
    const int bt = blockIdx.x;
    const int t  = threadIdx.x;
    __shared__ float rv[DR], e1v[DE], e2v[DE];
    __shared__ float u0[KDIM], v1[KDIM], v3[KDIM], m2[KDIM], q2[KDIM];

    if (t < DR) rv[t]  = g_rbn [bt * DR + t];
    if (t < DE) { e1v[t] = g_e1bn[bt * DE + t]; e2v[t] = g_e2bn[bt * DE + t]; }
    __syncthreads();

    for (int lin = t; lin < KDIM; lin += 256) {
        int u = lin / RK, w = lin % RK;
        float s0 = 0.f, s1 = 0.f, s3 = 0.f;
        for (int r = 0; r < DR; r++) {
            s0 += rv[r]  * f0[u * FSTR + r * RK + w];
            s1 += e1v[r] * f1[u * FSTR + r * RK + w];
            s3 += e2v[r] * f3[u * FSTR + r * RK + w];
        }
        u0[lin] = s0; v1[lin] = s1; v3[lin] = s3;
    }
    __syncthreads();

    for (int lin = t; lin < KDIM; lin += 256) {
        int a = lin / RK, c = lin % RK;
        float s = 0.f;
#pragma unroll
        for (int b = 0; b < RK; b++) s += u0[a * RK + b] * v1[b * RK + c];
        m2[lin] = s;
    }
    __syncthreads();

    for (int lin = t; lin < KDIM; lin += 256) {
        int c = lin / RK, d = lin % RK;
        float s = 0.f;
#pragma unroll
        for (int a = 0; a < RK; a++) s += m2[a * RK + c] * v3[d * RK + a];
        q2[lin] = s;
    }
    __syncthreads();

    if (t < DE) {
        float s = 0.f;
        for (int c = 0; c < RK; c++) {
            const float* f2row = f2 + c * FSTR + t * RK;
#pragma unroll
            for (int d = 0; d < RK; d++) s += q2[c * RK + d] * f2row[d];
        }
        g_wout[bt * DE + t] = s;
    }
}

// ---------------------------------------------------------------------
// scores v2: entity-tiled GEMM [128 bt x 100] @ [100 x 10000 ent].
// Block = 128 entities; Wt + Et staged in smem; 8x8 register tiles.
#define SC_SMEM ((BATCH * DE + BATCH * 101) * 4)
__global__ __launch_bounds__(256) void scores_kernel(const float* __restrict__ E)
{
    extern __shared__ float sh[];
    float* Wt = sh;                    // [128][100]
    float* Et = sh + BATCH * DE;       // [128][101] (pad vs bank conflicts)
    const int e0 = blockIdx.x * 128;
    const int ne = (NENT - e0 < 128) ? (NENT - e0) : 128;
    const int tid = threadIdx.x;

    for (int idx = tid; idx < BATCH * DE; idx += 256) Wt[idx] = g_woutbn[idx];
    for (int idx = tid; idx < ne * DE; idx += 256) {
        int r = idx / DE, c = idx % DE;
        Et[r * 101 + c] = E[(size_t)e0 * DE + idx];
    }
    __syncthreads();

    const int ty = tid >> 4;   // bt base (0..15)
    const int tx = tid & 15;   // ent base (0..15)
    float acc[8][8];
#pragma unroll
    for (int i = 0; i < 8; i++)
#pragma unroll
        for (int j = 0; j < 8; j++) acc[i][j] = 0.f;

    for (int i = 0; i < DE; i++) {
        float wb[8], ee[8];
#pragma unroll
        for (int k = 0; k < 8; k++) wb[k] = Wt[(ty + 16 * k) * DE + i];
#pragma unroll
        for (int k = 0; k < 8; k++) ee[k] = Et[(tx + 16 * k) * 101 + i];
#pragma unroll
        for (int kb = 0; kb < 8; kb++)
#pragma unroll
            for (int ke = 0; ke < 8; ke++) acc[kb][ke] += wb[kb] * ee[ke];
    }

#pragma unroll
    for (int kb = 0; kb < 8; kb++) {
        int bt = ty + 16 * kb;
#pragma unroll
        for (int ke = 0; ke < 8; ke++) {
            int e = tx + 16 * ke;
            if (e < ne) g_scores[(size_t)bt * NENT + e0 + e] = acc[kb][ke];
        }
    }
}

// ---------------------------------------------------------------------
__global__ __launch_bounds__(256) void softmax_kernel(float* __restrict__ pred)
{
    const int bt = blockIdx.x;
    const int t  = threadIdx.x;
    const float* row = g_scores + (size_t)bt * NENT;
    __shared__ float red[8];
    __shared__ float smx, ssumv;

    float mx = -1e30f;
    for (int e = t; e < NENT; e += 256) mx = fmaxf(mx, row[e]);
#pragma unroll
    for (int o = 16; o > 0; o >>= 1) mx = fmaxf(mx, __shfl_xor_sync(0xffffffffu, mx, o));
    if ((t & 31) == 0) red[t >> 5] = mx;
    __syncthreads();
    if (t == 0) {
        float m = red[0];
        for (int i = 1; i < 8; i++) m = fmaxf(m, red[i]);
        smx = m;
    }
    __syncthreads();
    mx = smx;

    float sum = 0.f;
    for (int e = t; e < NENT; e += 256) sum += expf(row[e] - mx);
#pragma unroll
    for (int o = 16; o > 0; o >>= 1) sum += __shfl_xor_sync(0xffffffffu, sum, o);
    __syncthreads();
    if ((t & 31) == 0) red[t >> 5] = sum;
    __syncthreads();
    if (t == 0) {
        float s = 0.f;
        for (int i = 0; i < 8; i++) s += red[i];
        ssumv = s;
    }
    __syncthreads();
    const float inv = 1.f / ssumv;
    for (int e = t; e < NENT; e += 256)
        pred[(size_t)bt * NENT + e] = expf(row[e] - mx) * inv;
}

// ---------------------------------------------------------------------
extern "C" void kernel_launch(void* const* d_in, const int* in_sizes, int n_in,
                              void* d_out, int out_size)
{
    const float* E     = (const float*)d_in[0];
    const float* R     = (const float*)d_in[1];
    const float* f0    = (const float*)d_in[2];
    const float* f1    = (const float*)d_in[3];
    const float* f2    = (const float*)d_in[4];
    const float* f3    = (const float*)d_in[5];
    const float* bnr_g = (const float*)d_in[6];
    const float* bnr_b = (const float*)d_in[7];
    const float* bne_g = (const float*)d_in[8];
    const float* bne_b = (const float*)d_in[9];
    const float* bnw_g = (const float*)d_in[10];
    const float* bnw_b = (const float*)d_in[11];
    const int*   r_idx = (const int*)d_in[12];
    const int*   e_idx1 = (const int*)d_in[13];
    const int*   e_idx2 = (const int*)d_in[14];

    float* outPred = (float*)d_out;                   // [128, 10000]
    float* outW    = outPred + (size_t)BATCH * NENT;  // [100^4]

    cudaFuncSetAttribute(tn_gemm, cudaFuncAttributeMaxDynamicSharedMemorySize, SMEM_TOTAL);
    cudaFuncSetAttribute(scores_kernel, cudaFuncAttributeMaxDynamicSharedMemorySize, SC_SMEM);

    // Launch order chosen so launch index 5 (ncu -s 5 -c 1) is tn_gemm.
    pair_contract<<<MN, 256>>>(f0, f1, 0);                       // 0
    pair_contract<<<MN, 256>>>(f2, f3, 1);                       // 1
    bn3_kernel<<<DR + 2 * DE, 128>>>(R, E, r_idx, e_idx1, e_idx2,
                                     bnr_g, bnr_b, bne_g, bne_b); // 2
    tr_wout_kernel<<<BATCH, 256>>>(f0, f1, f2, f3);              // 3
    bnw_kernel<<<DE, 128>>>(bnw_g, bnw_b);                       // 4
    dim3 grid((MN + BN - 1) / BN, (MN + BM - 1) / BM);           // 79 x 79
    tn_gemm<<<grid, 256, SMEM_TOTAL>>>(outW);                    // 5  <- profiled
    scores_kernel<<<(NENT + 127) / 128, 256, SC_SMEM>>>(E);      // 6
    softmax_kernel<<<BATCH, 256>>>(outPred);                     // 7
}